// round 2
// baseline (speedup 1.0000x reference)
#include <cuda_runtime.h>
#include <math.h>

#define T 2048
#define D 2048
#define NH 16
#define NKVH 4
#define HD 128
#define DH 1024          // D/2, router hidden
#define KVD 512          // NKVH*HD

// ---------------- scratch (no cudaMalloc allowed) ----------------
// layout (floats):
//   q      : [0,            4M)
//   l2     : [4M,           8M)
//   h      : [8M,          10M)
//   fused  : [10M,         14M)
//   k      : [14M,         15M)
//   v      : [15M,         16M)
//   attnout: [16M,         20M)
//   lam    : [20M,         20M+4096)
#define MEG (1024*1024)
__device__ float g_scratch[20 * MEG + 4096];

// ---------------- generic tiled fp32 GEMM: C = A[MxK] * B[KxN] (+bias, silu) ----
// 64x64 tile, 256 threads, 4x4 micro-tile, K-step 16. All dims multiples of 64/16.
template<int SILU>
__global__ void gemm64(const float* __restrict__ A, const float* __restrict__ B,
                       const float* __restrict__ bias, float* __restrict__ C,
                       int M, int N, int K) {
    __shared__ float As[16][65];
    __shared__ float Bs[16][68];
    const int tid = threadIdx.x;
    const int m0 = blockIdx.y * 64, n0 = blockIdx.x * 64;
    const int ar = tid >> 2, ak = (tid & 3) << 2;   // A: 64 rows x 16 k
    const int bk = tid >> 4, bn = (tid & 15) << 2;  // B: 16 k x 64 n
    const int tx = tid & 15, ty = tid >> 4;

    float c[4][4] = {};
    for (int k0 = 0; k0 < K; k0 += 16) {
        float4 av = *(const float4*)(A + (size_t)(m0 + ar) * K + k0 + ak);
        As[ak + 0][ar] = av.x; As[ak + 1][ar] = av.y;
        As[ak + 2][ar] = av.z; As[ak + 3][ar] = av.w;
        *(float4*)&Bs[bk][bn] = *(const float4*)(B + (size_t)(k0 + bk) * N + n0 + bn);
        __syncthreads();
        #pragma unroll
        for (int kk = 0; kk < 16; kk++) {
            float a[4], b[4];
            #pragma unroll
            for (int i = 0; i < 4; i++) a[i] = As[kk][ty * 4 + i];
            #pragma unroll
            for (int j = 0; j < 4; j++) b[j] = Bs[kk][tx * 4 + j];
            #pragma unroll
            for (int i = 0; i < 4; i++)
                #pragma unroll
                for (int j = 0; j < 4; j++)
                    c[i][j] += a[i] * b[j];
        }
        __syncthreads();
    }
    #pragma unroll
    for (int i = 0; i < 4; i++) {
        #pragma unroll
        for (int j = 0; j < 4; j++) {
            int col = n0 + tx * 4 + j;
            float val = c[i][j];
            if (bias) val += bias[col];
            if (SILU) val = val / (1.f + expf(-val));
            C[(size_t)(m0 + ty * 4 + i) * N + col] = val;
        }
    }
}

// ---------------- causal prefix EMA: m_t = b*m_{t-1} + (1-b)*x_t --------------
__global__ void ema_kernel(const float* __restrict__ x, float* __restrict__ l2) {
    int d = blockIdx.x * blockDim.x + threadIdx.x;
    if (d >= D) return;
    const float beta = 0.9f, ombeta = 1.0f - 0.9f;
    float m = 0.f;
    for (int t = 0; t < T; t++) {
        m = beta * m + ombeta * x[(size_t)t * D + d];
        l2[(size_t)t * D + d] = m;
    }
}

// ---------------- router: lam = softmax(h @ Wr2 + br2) (warp per row) --------
__global__ void router_kernel(const float* __restrict__ h, const float* __restrict__ Wr2,
                              const float* __restrict__ br2, float* __restrict__ lam) {
    int t = blockIdx.x * (blockDim.x >> 5) + (threadIdx.x >> 5);
    int lane = threadIdx.x & 31;
    if (t >= T) return;
    const float* hp = h + (size_t)t * DH;
    float z0 = 0.f, z1 = 0.f;
    for (int i = lane; i < DH; i += 32) {
        float hv = hp[i];
        z0 += hv * Wr2[i * 2 + 0];
        z1 += hv * Wr2[i * 2 + 1];
    }
    #pragma unroll
    for (int off = 16; off; off >>= 1) {
        z0 += __shfl_xor_sync(0xffffffffu, z0, off);
        z1 += __shfl_xor_sync(0xffffffffu, z1, off);
    }
    if (lane == 0) {
        z0 += br2[0]; z1 += br2[1];
        float mx = fmaxf(z0, z1);
        float e0 = expf(z0 - mx), e1 = expf(z1 - mx);
        float inv = 1.f / (e0 + e1);
        lam[t * 2 + 0] = e0 * inv;
        lam[t * 2 + 1] = e1 * inv;
    }
}

// ---------------- fused = lam0 * x + lam1 * l2 -------------------------------
__global__ void fuse_kernel(const float* __restrict__ x, const float* __restrict__ l2,
                            const float* __restrict__ lam, float* __restrict__ fused) {
    int idx = blockIdx.x * blockDim.x + threadIdx.x;
    if (idx >= T * D) return;
    int t = idx >> 11;  // /D (D=2048)
    fused[idx] = lam[t * 2] * x[idx] + lam[t * 2 + 1] * l2[idx];
}

// ---------------- RoPE in place (layout: [t][head*128 + d]) ------------------
__global__ void rope_kernel(float* __restrict__ x, int heads) {
    int idx = blockIdx.x * blockDim.x + threadIdx.x;
    int total = T * heads * 64;
    if (idx >= total) return;
    int j = idx & 63;
    int hh = (idx >> 6) % heads;
    int t = idx / (heads * 64);
    float* p = x + (size_t)t * heads * HD + hh * HD;
    // inv_freq = 10000^(-2j/128)
    float inv = expf(-9.210340371976184f * (2.f * j / 128.f));  // ln(10000)=9.2103...
    float ang = (float)t * inv;
    float cs = cosf(ang), sn = sinf(ang);
    float a = p[j], b = p[j + 64];
    p[j]      = a * cs - b * sn;
    p[j + 64] = b * cs + a * sn;
}

// ---------------- causal GQA attention: warp per query row -------------------
__global__ void attn_kernel(const float* __restrict__ q, const float* __restrict__ k,
                            const float* __restrict__ v, float* __restrict__ o) {
    int head = blockIdx.y;
    int warp = threadIdx.x >> 5, lane = threadIdx.x & 31;
    int row = blockIdx.x * 4 + warp;
    int kvh = head >> 2;  // H/KVH = 4 repeats

    const float* qp = q + (size_t)row * D + head * HD;
    float qr[4];
    #pragma unroll
    for (int i = 0; i < 4; i++) qr[i] = qp[lane + 32 * i];

    const float scale = 0.08838834764831845f;  // 1/sqrt(128)
    float m = -1e30f, l = 0.f, acc[4] = {0.f, 0.f, 0.f, 0.f};

    for (int j = 0; j <= row; j++) {
        const float* kp = k + (size_t)j * KVD + kvh * HD;
        float s = qr[0] * kp[lane]      + qr[1] * kp[lane + 32]
                + qr[2] * kp[lane + 64] + qr[3] * kp[lane + 96];
        #pragma unroll
        for (int off = 16; off; off >>= 1) s += __shfl_xor_sync(0xffffffffu, s, off);
        s *= scale;
        float mn = fmaxf(m, s);
        float corr = __expf(m - mn);
        float p = __expf(s - mn);
        l = l * corr + p;
        const float* vp = v + (size_t)j * KVD + kvh * HD;
        #pragma unroll
        for (int i = 0; i < 4; i++) acc[i] = acc[i] * corr + p * vp[lane + 32 * i];
        m = mn;
    }
    float invl = 1.f / l;
    float* op = o + (size_t)row * D + head * HD;
    #pragma unroll
    for (int i = 0; i < 4; i++) op[lane + 32 * i] = acc[i] * invl;
}

// ---------------- launcher ---------------------------------------------------
extern "C" void kernel_launch(void* const* d_in, const int* in_sizes, int n_in,
                              void* d_out, int out_size) {
    const float* hs  = (const float*)d_in[0];
    const float* Wq  = (const float*)d_in[1];
    const float* Wk  = (const float*)d_in[2];
    const float* Wv  = (const float*)d_in[3];
    const float* Wo  = (const float*)d_in[4];
    const float* Wr1 = (const float*)d_in[5];
    const float* br1 = (const float*)d_in[6];
    const float* Wr2 = (const float*)d_in[7];
    const float* br2 = (const float*)d_in[8];
    float* out = (float*)d_out;

    float* S;
    cudaGetSymbolAddress((void**)&S, g_scratch);
    float* q     = S;
    float* l2    = S + 4 * MEG;
    float* h     = S + 8 * MEG;
    float* fused = S + 10 * MEG;
    float* k     = S + 14 * MEG;
    float* v     = S + 15 * MEG;
    float* ao    = S + 16 * MEG;
    float* lam   = S + 20 * MEG;

    // q = hs @ Wq  (2048 x 2048 x 2048)
    gemm64<0><<<dim3(D / 64, T / 64), 256>>>(hs, Wq, nullptr, q, T, D, D);
    // l2 = causal EMA(hs)
    ema_kernel<<<D / 256, 256>>>(hs, l2);
    // h = silu(q @ Wr1 + br1)   (2048 x 1024 x 2048)
    gemm64<1><<<dim3(DH / 64, T / 64), 256>>>(q, Wr1, br1, h, T, DH, D);
    // lam = softmax(h @ Wr2 + br2)
    router_kernel<<<T / 8, 256>>>(h, Wr2, br2, lam);
    // fused = lam0*hs + lam1*l2
    fuse_kernel<<<(T * D + 255) / 256, 256>>>(hs, l2, lam, fused);
    // k/v = fused @ Wk/Wv   (2048 x 512 x 2048)
    gemm64<0><<<dim3(KVD / 64, T / 64), 256>>>(fused, Wk, nullptr, k, T, KVD, D);
    gemm64<0><<<dim3(KVD / 64, T / 64), 256>>>(fused, Wv, nullptr, v, T, KVD, D);
    // RoPE in place on q (16 heads) and k (4 heads)
    rope_kernel<<<(T * NH * 64 + 255) / 256, 256>>>(q, NH);
    rope_kernel<<<(T * NKVH * 64 + 255) / 256, 256>>>(k, NKVH);
    // causal GQA attention
    attn_kernel<<<dim3(T / 4, NH), 128>>>(q, k, v, ao);
    // out = ao @ Wo   (2048 x 2048 x 2048)
    gemm64<0><<<dim3(D / 64, T / 64), 256>>>(ao, Wo, nullptr, out, T, D, D);
}

// round 7
// speedup vs baseline: 1.1548x; 1.1548x over previous
#include <cuda_runtime.h>
#include <cuda_bf16.h>
#include <math.h>
#include <stdint.h>

#define T 2048
#define D 2048
#define NH 16
#define NKVH 4
#define HD 128
#define DH 1024
#define KVD 512
#define MEG (1024*1024)

// scratch (floats): q[0,4M) l2[4M,8M) h[8M,10M) fused[10M,14M) k[14M,15M)
// v[15M,16M) ao[16M,20M) lam/carry/cpref[20M,20M+128K)
// Ahi[20M+128K, +2M) Alo[22M+128K, +2M) Whi[24M+128K, +2M) Wlo[26M+128K, +2M)
__device__ float g_scratch[29 * MEG];

// ================= PTX helpers (non-'a' features only) =================
__device__ __forceinline__ uint32_t smem_u32(const void* p) {
    uint32_t a;
    asm("{ .reg .u64 t; cvta.to.shared.u64 t, %1; cvt.u32.u64 %0, t; }" : "=r"(a) : "l"(p));
    return a;
}
#define CP16(s, g) asm volatile("cp.async.cg.shared.global [%0], [%1], 16;" \
    :: "r"(s), "l"(__cvta_generic_to_global(g)) : "memory")
#define CP_COMMIT() asm volatile("cp.async.commit_group;" ::: "memory")
#define CP_WAIT(n)  asm volatile("cp.async.wait_group %0;" :: "n"(n) : "memory")

__device__ __forceinline__ void ldsm_x4(uint32_t* r, uint32_t addr) {
    asm volatile("ldmatrix.sync.aligned.m8n8.x4.shared.b16 {%0,%1,%2,%3}, [%4];"
        : "=r"(r[0]), "=r"(r[1]), "=r"(r[2]), "=r"(r[3]) : "r"(addr));
}
__device__ __forceinline__ void mma16816(float* d, const uint32_t* a, uint32_t b0, uint32_t b1) {
    asm volatile("mma.sync.aligned.m16n8k16.row.col.f32.bf16.bf16.f32 "
        "{%0,%1,%2,%3}, {%4,%5,%6,%7}, {%8,%9}, {%0,%1,%2,%3};"
        : "+f"(d[0]), "+f"(d[1]), "+f"(d[2]), "+f"(d[3])
        : "r"(a[0]), "r"(a[1]), "r"(a[2]), "r"(a[3]), "r"(b0), "r"(b1));
}

// ================= convert: fp32 -> bf16 hi/lo (elementwise) =================
__global__ void conv_a(const float* __restrict__ A, __nv_bfloat16* __restrict__ hi,
                       __nv_bfloat16* __restrict__ lo, int n4) {
    int i = blockIdx.x * blockDim.x + threadIdx.x;
    if (i >= n4) return;
    float4 a = ((const float4*)A)[i];
    __nv_bfloat162 h0 = __floats2bfloat162_rn(a.x, a.y);
    __nv_bfloat162 h1 = __floats2bfloat162_rn(a.z, a.w);
    __nv_bfloat162 l0 = __floats2bfloat162_rn(a.x - __bfloat162float(h0.x), a.y - __bfloat162float(h0.y));
    __nv_bfloat162 l1 = __floats2bfloat162_rn(a.z - __bfloat162float(h1.x), a.w - __bfloat162float(h1.y));
    ((__nv_bfloat162*)hi)[2 * i]     = h0;
    ((__nv_bfloat162*)hi)[2 * i + 1] = h1;
    ((__nv_bfloat162*)lo)[2 * i]     = l0;
    ((__nv_bfloat162*)lo)[2 * i + 1] = l1;
}

// ========== convert + transpose weights: W[K,N] fp32 -> Wt[N,K] bf16 hi/lo ==========
__global__ void conv_wt(const float* __restrict__ W, __nv_bfloat16* __restrict__ hi,
                        __nv_bfloat16* __restrict__ lo, int Kd, int Nd) {
    __shared__ float tile[32][33];
    int nb = blockIdx.x * 32, kb = blockIdx.y * 32;
    int tx = threadIdx.x & 31, ty0 = threadIdx.x >> 5;
    #pragma unroll
    for (int i = 0; i < 4; i++)
        tile[ty0 + 8 * i][tx] = W[(size_t)(kb + ty0 + 8 * i) * Nd + nb + tx];
    __syncthreads();
    #pragma unroll
    for (int i = 0; i < 4; i++) {
        int r = ty0 + 8 * i;
        float v = tile[tx][r];
        __nv_bfloat16 h = __float2bfloat16_rn(v);
        __nv_bfloat16 l = __float2bfloat16_rn(v - __bfloat162float(h));
        size_t o = (size_t)(nb + r) * Kd + kb + tx;
        hi[o] = h;
        lo[o] = l;
    }
}

// ================= bf16-split HMMA GEMM: C = A @ B (+bias,silu) =================
// A given as hi/lo bf16 [M,K]; B given as transposed hi/lo bf16 [N,K].
// CTA 256 thr, tile 128x128, K-chunk 32, double-buffered cp.async.
// SMEM per buf: Ahi/Alo/Bhi/Blo each 128 rows x 80B (32 bf16 + 16B pad) = 10240B.
#define SM_STRIDE 80
#define SM_SPLIT 10240
#define SM_BUF 40960
#define SMEMB 81920

template<int ACT>
__global__ __launch_bounds__(256, 1)
void gemm_mma(const __nv_bfloat16* __restrict__ Ahi, const __nv_bfloat16* __restrict__ Alo,
              const __nv_bfloat16* __restrict__ Bhi, const __nv_bfloat16* __restrict__ Blo,
              const float* __restrict__ bias, float* __restrict__ C,
              int M, int N, int K,
              const __nv_bfloat16* B2hi, const __nv_bfloat16* B2lo, float* C2) {
    extern __shared__ char smem[];
    if (blockIdx.z) { Bhi = B2hi; Blo = B2lo; C = C2; }
    const int tid = threadIdx.x, wid = tid >> 5, lane = tid & 31;
    const int m0 = blockIdx.y * 128, n0 = blockIdx.x * 128;
    const int wm = wid >> 2, wn = wid & 3;
    const uint32_t sb = smem_u32(smem);

    // per-thread fill coordinates: 512 16B-chunks per split, 2 per thread
    const int r0c = tid >> 2, c0c = (tid & 3);        // chunk 0: row, 16B-col
    const int r1c = (tid + 256) >> 2, c1c = (tid & 3);

    auto fill = [&](int buf, int kc) {
        const int k0 = kc << 5;
        const uint32_t s0 = sb + buf * SM_BUF;
        uint32_t so0 = r0c * SM_STRIDE + c0c * 16;
        uint32_t so1 = r1c * SM_STRIDE + c1c * 16;
        const __nv_bfloat16* a0 = Ahi + (size_t)(m0 + r0c) * K + k0 + c0c * 8;
        const __nv_bfloat16* a1 = Ahi + (size_t)(m0 + r1c) * K + k0 + c1c * 8;
        const __nv_bfloat16* b0 = Bhi + (size_t)(n0 + r0c) * K + k0 + c0c * 8;
        const __nv_bfloat16* b1 = Bhi + (size_t)(n0 + r1c) * K + k0 + c1c * 8;
        size_t dAL = (size_t)(Alo - Ahi), dBL = (size_t)(Blo - Bhi);
        CP16(s0 + so0, a0); CP16(s0 + so1, a1);
        CP16(s0 + SM_SPLIT + so0, a0 + dAL); CP16(s0 + SM_SPLIT + so1, a1 + dAL);
        CP16(s0 + 2 * SM_SPLIT + so0, b0); CP16(s0 + 2 * SM_SPLIT + so1, b1);
        CP16(s0 + 3 * SM_SPLIT + so0, b0 + dBL); CP16(s0 + 3 * SM_SPLIT + so1, b1 + dBL);
        CP_COMMIT();
    };

    float acc[4][4][4] = {};
    const int KC = K >> 5;
    fill(0, 0);
    for (int kc = 0; kc < KC; kc++) {
        if (kc + 1 < KC) { fill((kc + 1) & 1, kc + 1); CP_WAIT(1); }
        else             { CP_WAIT(0); }
        __syncthreads();
        const uint32_t base = sb + (kc & 1) * SM_BUF;
        const uint32_t lrow = (lane & 15), lcol = (lane >> 4) * 16;
        #pragma unroll
        for (int kh = 0; kh < 2; kh++) {
            uint32_t ahi[4][4], alo[4][4], bhi[2][4], blo[2][4];
            #pragma unroll
            for (int mt = 0; mt < 4; mt++) {
                uint32_t ra = base + (wm * 64 + mt * 16 + lrow) * SM_STRIDE + kh * 32 + lcol;
                ldsm_x4(ahi[mt], ra);
                ldsm_x4(alo[mt], ra + SM_SPLIT);
            }
            #pragma unroll
            for (int nt = 0; nt < 2; nt++) {
                uint32_t rb = base + 2 * SM_SPLIT + (wn * 32 + nt * 16 + lrow) * SM_STRIDE + kh * 32 + lcol;
                ldsm_x4(bhi[nt], rb);
                ldsm_x4(blo[nt], rb + SM_SPLIT);
            }
            #pragma unroll
            for (int mt = 0; mt < 4; mt++)
                #pragma unroll
                for (int j = 0; j < 4; j++) {
                    uint32_t bh0 = bhi[j >> 1][j & 1], bh1 = bhi[j >> 1][2 + (j & 1)];
                    uint32_t bl0 = blo[j >> 1][j & 1], bl1 = blo[j >> 1][2 + (j & 1)];
                    mma16816(acc[mt][j], ahi[mt], bh0, bh1);
                    mma16816(acc[mt][j], ahi[mt], bl0, bl1);
                    mma16816(acc[mt][j], alo[mt], bh0, bh1);
                }
        }
        __syncthreads();
    }

    // epilogue
    const int erow = m0 + wm * 64 + (lane >> 2);
    const int ecol = n0 + wn * 32 + (lane & 3) * 2;
    #pragma unroll
    for (int mt = 0; mt < 4; mt++)
        #pragma unroll
        for (int j = 0; j < 4; j++) {
            int r = erow + mt * 16, c = ecol + j * 8;
            float v0 = acc[mt][j][0], v1 = acc[mt][j][1];
            float v2 = acc[mt][j][2], v3 = acc[mt][j][3];
            if (ACT) {
                float b0 = bias[c], b1 = bias[c + 1];
                v0 += b0; v1 += b1; v2 += b0; v3 += b1;
                v0 = v0 / (1.f + expf(-v0)); v1 = v1 / (1.f + expf(-v1));
                v2 = v2 / (1.f + expf(-v2)); v3 = v3 / (1.f + expf(-v3));
            }
            *(float2*)(C + (size_t)r * N + c)       = make_float2(v0, v1);
            *(float2*)(C + (size_t)(r + 8) * N + c) = make_float2(v2, v3);
        }
}

// ================= chunked causal EMA =================
__global__ void ema1_kernel(const float* __restrict__ x, float* __restrict__ l2,
                            float* __restrict__ carry) {
    int c = blockIdx.x;
    int d = blockIdx.y * 256 + threadIdx.x;
    const float beta = 0.9f, om = 0.1f;
    float m = 0.f;
    int t0 = c * 128;
    for (int t = t0; t < t0 + 128; t++) {
        m = beta * m + om * x[(size_t)t * D + d];
        l2[(size_t)t * D + d] = m;
    }
    carry[c * D + d] = m;
}
__global__ void ema2_kernel(const float* __restrict__ carry, float* __restrict__ cpref) {
    int d = blockIdx.x * 256 + threadIdx.x;
    const float b128 = 1.3900845e-06f;  // 0.9^128
    float p = 0.f;
    #pragma unroll
    for (int c = 0; c < 16; c++) {
        cpref[c * D + d] = p;
        p = carry[c * D + d] + b128 * p;
    }
}

// ================= router =================
__global__ void router_kernel(const float* __restrict__ h, const float* __restrict__ Wr2,
                              const float* __restrict__ br2, float* __restrict__ lam) {
    int t = blockIdx.x * (blockDim.x >> 5) + (threadIdx.x >> 5);
    int lane = threadIdx.x & 31;
    if (t >= T) return;
    const float* hp = h + (size_t)t * DH;
    float z0 = 0.f, z1 = 0.f;
    for (int i = lane; i < DH; i += 32) {
        float hv = hp[i];
        z0 += hv * Wr2[i * 2 + 0];
        z1 += hv * Wr2[i * 2 + 1];
    }
    #pragma unroll
    for (int off = 16; off; off >>= 1) {
        z0 += __shfl_xor_sync(0xffffffffu, z0, off);
        z1 += __shfl_xor_sync(0xffffffffu, z1, off);
    }
    if (lane == 0) {
        z0 += br2[0]; z1 += br2[1];
        float mx = fmaxf(z0, z1);
        float e0 = expf(z0 - mx), e1 = expf(z1 - mx);
        float inv = 1.f / (e0 + e1);
        lam[t * 2 + 0] = e0 * inv;
        lam[t * 2 + 1] = e1 * inv;
    }
}

// ====== fuse (with EMA carry fixup): fused = lam0*x + lam1*(l2 + b^(tl+1)*pref) ======
__global__ void fuse_kernel(const float* __restrict__ x, const float* __restrict__ l2,
                            const float* __restrict__ cpref, const float* __restrict__ lam,
                            float* __restrict__ fused) {
    int idx = blockIdx.x * blockDim.x + threadIdx.x;
    if (idx >= T * D) return;
    int t = idx >> 11, d = idx & 2047;
    int c = t >> 7, tl = t & 127;
    const float LOGB = -0.10536051565f;  // ln(0.9)
    float l2v = l2[idx] + __expf((float)(tl + 1) * LOGB) * cpref[c * D + d];
    fused[idx] = lam[t * 2] * x[idx] + lam[t * 2 + 1] * l2v;
}

// ================= RoPE in place =================
__global__ void rope_kernel(float* __restrict__ x, int heads) {
    int idx = blockIdx.x * blockDim.x + threadIdx.x;
    int total = T * heads * 64;
    if (idx >= total) return;
    int j = idx & 63;
    int hh = (idx >> 6) % heads;
    int t = idx / (heads * 64);
    float* p = x + (size_t)t * heads * HD + hh * HD;
    float inv = expf(-9.210340371976184f * (2.f * j / 128.f));
    float ang = (float)t * inv;
    float cs = cosf(ang), sn = sinf(ang);
    float a = p[j], b = p[j + 64];
    p[j]      = a * cs - b * sn;
    p[j + 64] = b * cs + a * sn;
}

// ================= causal GQA attention =================
__global__ void attn_kernel(const float* __restrict__ q, const float* __restrict__ k,
                            const float* __restrict__ v, float* __restrict__ o) {
    int head = blockIdx.y;
    int warp = threadIdx.x >> 5, lane = threadIdx.x & 31;
    int row = blockIdx.x * 4 + warp;
    int kvh = head >> 2;
    int s = lane & 7;
    int g = lane >> 3;

    const float* qp = q + (size_t)row * D + head * HD + s * 16;
    float4 q0 = *(const float4*)(qp);
    float4 q1 = *(const float4*)(qp + 4);
    float4 q2 = *(const float4*)(qp + 8);
    float4 q3 = *(const float4*)(qp + 12);

    const float* kbase = k + kvh * HD;
    const float* vbase = v + kvh * HD;
    const float scale = 0.08838834764831845f;
    float m = -1e30f, l = 0.f;
    float acc0 = 0.f, acc1 = 0.f, acc2 = 0.f, acc3 = 0.f;

    int j = 0;
    for (; j + 3 <= row; j += 4) {
        const float* kp = kbase + (size_t)(j + g) * KVD + s * 16;
        float4 k0 = *(const float4*)(kp);
        float4 k1 = *(const float4*)(kp + 4);
        float4 k2 = *(const float4*)(kp + 8);
        float4 k3 = *(const float4*)(kp + 12);
        float sp = q0.x * k0.x + q0.y * k0.y + q0.z * k0.z + q0.w * k0.w
                 + q1.x * k1.x + q1.y * k1.y + q1.z * k1.z + q1.w * k1.w
                 + q2.x * k2.x + q2.y * k2.y + q2.z * k2.z + q2.w * k2.w
                 + q3.x * k3.x + q3.y * k3.y + q3.z * k3.z + q3.w * k3.w;
        sp += __shfl_xor_sync(0xffffffffu, sp, 1);
        sp += __shfl_xor_sync(0xffffffffu, sp, 2);
        sp += __shfl_xor_sync(0xffffffffu, sp, 4);
        float s0 = __shfl_sync(0xffffffffu, sp, 0)  * scale;
        float s1 = __shfl_sync(0xffffffffu, sp, 8)  * scale;
        float s2 = __shfl_sync(0xffffffffu, sp, 16) * scale;
        float s3 = __shfl_sync(0xffffffffu, sp, 24) * scale;
        float mn = fmaxf(fmaxf(fmaxf(s0, s1), fmaxf(s2, s3)), m);
        float corr = __expf(m - mn);
        float p0 = __expf(s0 - mn), p1 = __expf(s1 - mn);
        float p2 = __expf(s2 - mn), p3 = __expf(s3 - mn);
        l = l * corr + (p0 + p1 + p2 + p3);
        const float* vp0 = vbase + (size_t)(j + 0) * KVD;
        const float* vp1 = vbase + (size_t)(j + 1) * KVD;
        const float* vp2 = vbase + (size_t)(j + 2) * KVD;
        const float* vp3 = vbase + (size_t)(j + 3) * KVD;
        acc0 = acc0 * corr + p0 * vp0[lane]      + p1 * vp1[lane]      + p2 * vp2[lane]      + p3 * vp3[lane];
        acc1 = acc1 * corr + p0 * vp0[lane + 32] + p1 * vp1[lane + 32] + p2 * vp2[lane + 32] + p3 * vp3[lane + 32];
        acc2 = acc2 * corr + p0 * vp0[lane + 64] + p1 * vp1[lane + 64] + p2 * vp2[lane + 64] + p3 * vp3[lane + 64];
        acc3 = acc3 * corr + p0 * vp0[lane + 96] + p1 * vp1[lane + 96] + p2 * vp2[lane + 96] + p3 * vp3[lane + 96];
        m = mn;
    }
    for (; j <= row; j++) {
        const float* kp = kbase + (size_t)j * KVD + s * 16;
        float4 k0 = *(const float4*)(kp);
        float4 k1 = *(const float4*)(kp + 4);
        float4 k2 = *(const float4*)(kp + 8);
        float4 k3 = *(const float4*)(kp + 12);
        float sp = q0.x * k0.x + q0.y * k0.y + q0.z * k0.z + q0.w * k0.w
                 + q1.x * k1.x + q1.y * k1.y + q1.z * k1.z + q1.w * k1.w
                 + q2.x * k2.x + q2.y * k2.y + q2.z * k2.z + q2.w * k2.w
                 + q3.x * k3.x + q3.y * k3.y + q3.z * k3.z + q3.w * k3.w;
        sp += __shfl_xor_sync(0xffffffffu, sp, 1);
        sp += __shfl_xor_sync(0xffffffffu, sp, 2);
        sp += __shfl_xor_sync(0xffffffffu, sp, 4);
        float sc = sp * scale;
        float mn = fmaxf(m, sc);
        float corr = __expf(m - mn);
        float p = __expf(sc - mn);
        l = l * corr + p;
        const float* vp = vbase + (size_t)j * KVD;
        acc0 = acc0 * corr + p * vp[lane];
        acc1 = acc1 * corr + p * vp[lane + 32];
        acc2 = acc2 * corr + p * vp[lane + 64];
        acc3 = acc3 * corr + p * vp[lane + 96];
        m = mn;
    }
    float invl = 1.f / l;
    float* op = o + (size_t)row * D + head * HD;
    op[lane]      = acc0 * invl;
    op[lane + 32] = acc1 * invl;
    op[lane + 64] = acc2 * invl;
    op[lane + 96] = acc3 * invl;
}

// ================= launcher =================
extern "C" void kernel_launch(void* const* d_in, const int* in_sizes, int n_in,
                              void* d_out, int out_size) {
    const float* hs  = (const float*)d_in[0];
    const float* Wq  = (const float*)d_in[1];
    const float* Wk  = (const float*)d_in[2];
    const float* Wv  = (const float*)d_in[3];
    const float* Wo  = (const float*)d_in[4];
    const float* Wr1 = (const float*)d_in[5];
    const float* br1 = (const float*)d_in[6];
    const float* Wr2 = (const float*)d_in[7];
    const float* br2 = (const float*)d_in[8];
    float* out = (float*)d_out;

    float* S;
    cudaGetSymbolAddress((void**)&S, g_scratch);
    float* q     = S;
    float* l2    = S + 4 * MEG;
    float* h     = S + 8 * MEG;
    float* fused = S + 10 * MEG;
    float* kbuf  = S + 14 * MEG;
    float* vbuf  = S + 15 * MEG;
    float* ao    = S + 16 * MEG;
    float* lam   = S + 20 * MEG;
    float* carry = lam + 4096;
    float* cpref = carry + 32768;
    __nv_bfloat16* Ahi = (__nv_bfloat16*)(S + 20 * MEG + 131072);
    __nv_bfloat16* Alo = (__nv_bfloat16*)(S + 22 * MEG + 131072);
    __nv_bfloat16* Whi = (__nv_bfloat16*)(S + 24 * MEG + 131072);
    __nv_bfloat16* Wlo = (__nv_bfloat16*)(S + 26 * MEG + 131072);

    cudaFuncSetAttribute(gemm_mma<0>, cudaFuncAttributeMaxDynamicSharedMemorySize, SMEMB);
    cudaFuncSetAttribute(gemm_mma<1>, cudaFuncAttributeMaxDynamicSharedMemorySize, SMEMB);

    // ---- q = hs @ Wq ----
    conv_a<<<(T * D / 4 + 255) / 256, 256>>>(hs, Ahi, Alo, T * D / 4);
    conv_wt<<<dim3(D / 32, D / 32), 256>>>(Wq, Whi, Wlo, D, D);
    gemm_mma<0><<<dim3(D / 128, T / 128, 1), 256, SMEMB>>>(
        Ahi, Alo, Whi, Wlo, nullptr, q, T, D, D, nullptr, nullptr, nullptr);

    // ---- EMA ----
    ema1_kernel<<<dim3(16, 8), 256>>>(hs, l2, carry);
    ema2_kernel<<<8, 256>>>(carry, cpref);

    // ---- h = silu(q @ Wr1 + br1) ----
    conv_a<<<(T * D / 4 + 255) / 256, 256>>>(q, Ahi, Alo, T * D / 4);
    conv_wt<<<dim3(DH / 32, D / 32), 256>>>(Wr1, Whi, Wlo, D, DH);
    gemm_mma<1><<<dim3(DH / 128, T / 128, 1), 256, SMEMB>>>(
        Ahi, Alo, Whi, Wlo, br1, h, T, DH, D, nullptr, nullptr, nullptr);

    // ---- lam, fused ----
    router_kernel<<<T / 8, 256>>>(h, Wr2, br2, lam);
    fuse_kernel<<<(T * D + 255) / 256, 256>>>(hs, l2, cpref, lam, fused);

    // ---- k = fused @ Wk, v = fused @ Wv ----
    conv_a<<<(T * D / 4 + 255) / 256, 256>>>(fused, Ahi, Alo, T * D / 4);
    __nv_bfloat16* WkHi = Whi;
    __nv_bfloat16* WkLo = Whi + KVD * D;   // 1M bf16
    __nv_bfloat16* WvHi = Wlo;
    __nv_bfloat16* WvLo = Wlo + KVD * D;
    conv_wt<<<dim3(KVD / 32, D / 32), 256>>>(Wk, WkHi, WkLo, D, KVD);
    conv_wt<<<dim3(KVD / 32, D / 32), 256>>>(Wv, WvHi, WvLo, D, KVD);
    gemm_mma<0><<<dim3(KVD / 128, T / 128, 2), 256, SMEMB>>>(
        Ahi, Alo, WkHi, WkLo, nullptr, kbuf, T, KVD, D, WvHi, WvLo, vbuf);

    // ---- RoPE ----
    rope_kernel<<<(T * NH * 64 + 255) / 256, 256>>>(q, NH);
    rope_kernel<<<(T * NKVH * 64 + 255) / 256, 256>>>(kbuf, NKVH);

    // ---- attention ----
    attn_kernel<<<dim3(T / 4, NH), 128>>>(q, kbuf, vbuf, ao);

    // ---- out = ao @ Wo ----
    conv_a<<<(T * D / 4 + 255) / 256, 256>>>(ao, Ahi, Alo, T * D / 4);
    conv_wt<<<dim3(D / 32, D / 32), 256>>>(Wo, Whi, Wlo, D, D);
    gemm_mma<0><<<dim3(D / 128, T / 128, 1), 256, SMEMB>>>(
        Ahi, Alo, Whi, Wlo, nullptr, out, T, D, D, nullptr, nullptr, nullptr);
}

// round 8
// speedup vs baseline: 4.4127x; 3.8212x over previous
#include <cuda_runtime.h>
#include <cuda_bf16.h>
#include <math.h>
#include <stdint.h>

#define T 2048
#define D 2048
#define NH 16
#define NKVH 4
#define HD 128
#define DH 1024
#define KVD 512
#define MEG (1024*1024)

// scratch (floats): q[0,4M) l2[4M,8M) h[8M,10M) fused[10M,14M) k[14M,15M)
// v[15M,16M) ao[16M,20M) lam/carry/cpref[20M,+128K)
// Ahi[20M+128K) Alo[22M+128K) Whi[24M+128K) Wlo[26M+128K)
// Qhi[29M) Qlo[31M) Khi[33M) Klo[33.5M) Vhi[34M) Vlo[34.5M)
__device__ float g_scratch[35 * MEG];

// ================= PTX helpers =================
__device__ __forceinline__ uint32_t smem_u32(const void* p) {
    uint32_t a;
    asm("{ .reg .u64 t; cvta.to.shared.u64 t, %1; cvt.u32.u64 %0, t; }" : "=r"(a) : "l"(p));
    return a;
}
#define CP16(s, g) asm volatile("cp.async.cg.shared.global [%0], [%1], 16;" \
    :: "r"(s), "l"(__cvta_generic_to_global(g)) : "memory")
#define CP_COMMIT() asm volatile("cp.async.commit_group;" ::: "memory")
#define CP_WAIT(n)  asm volatile("cp.async.wait_group %0;" :: "n"(n) : "memory")

__device__ __forceinline__ void ldsm_x4(uint32_t* r, uint32_t addr) {
    asm volatile("ldmatrix.sync.aligned.m8n8.x4.shared.b16 {%0,%1,%2,%3}, [%4];"
        : "=r"(r[0]), "=r"(r[1]), "=r"(r[2]), "=r"(r[3]) : "r"(addr));
}
__device__ __forceinline__ void ldsm_x4_t(uint32_t* r, uint32_t addr) {
    asm volatile("ldmatrix.sync.aligned.m8n8.x4.trans.shared.b16 {%0,%1,%2,%3}, [%4];"
        : "=r"(r[0]), "=r"(r[1]), "=r"(r[2]), "=r"(r[3]) : "r"(addr));
}
__device__ __forceinline__ void mma16816(float* d, const uint32_t* a, uint32_t b0, uint32_t b1) {
    asm volatile("mma.sync.aligned.m16n8k16.row.col.f32.bf16.bf16.f32 "
        "{%0,%1,%2,%3}, {%4,%5,%6,%7}, {%8,%9}, {%0,%1,%2,%3};"
        : "+f"(d[0]), "+f"(d[1]), "+f"(d[2]), "+f"(d[3])
        : "r"(a[0]), "r"(a[1]), "r"(a[2]), "r"(a[3]), "r"(b0), "r"(b1));
}
__device__ __forceinline__ float ex2(float x) {
    float y; asm("ex2.approx.ftz.f32 %0, %1;" : "=f"(y) : "f"(x)); return y;
}
__device__ __forceinline__ void hilo2(float a, float b, uint32_t& hi, uint32_t& lo) {
    __nv_bfloat162 h = __floats2bfloat162_rn(a, b);
    __nv_bfloat162 l = __floats2bfloat162_rn(a - __bfloat162float(h.x), b - __bfloat162float(h.y));
    hi = *(uint32_t*)&h; lo = *(uint32_t*)&l;
}

// ================= convert: fp32 -> bf16 hi/lo =================
__global__ void conv_a(const float* __restrict__ A, __nv_bfloat16* __restrict__ hi,
                       __nv_bfloat16* __restrict__ lo, int n4) {
    int i = blockIdx.x * blockDim.x + threadIdx.x;
    if (i >= n4) return;
    float4 a = ((const float4*)A)[i];
    __nv_bfloat162 h0 = __floats2bfloat162_rn(a.x, a.y);
    __nv_bfloat162 h1 = __floats2bfloat162_rn(a.z, a.w);
    __nv_bfloat162 l0 = __floats2bfloat162_rn(a.x - __bfloat162float(h0.x), a.y - __bfloat162float(h0.y));
    __nv_bfloat162 l1 = __floats2bfloat162_rn(a.z - __bfloat162float(h1.x), a.w - __bfloat162float(h1.y));
    ((__nv_bfloat162*)hi)[2 * i]     = h0;
    ((__nv_bfloat162*)hi)[2 * i + 1] = h1;
    ((__nv_bfloat162*)lo)[2 * i]     = l0;
    ((__nv_bfloat162*)lo)[2 * i + 1] = l1;
}

// ========== convert + transpose weights: W[K,N] -> Wt[N,K] bf16 hi/lo ==========
__global__ void conv_wt(const float* __restrict__ W, __nv_bfloat16* __restrict__ hi,
                        __nv_bfloat16* __restrict__ lo, int Kd, int Nd) {
    __shared__ float tile[32][33];
    int nb = blockIdx.x * 32, kb = blockIdx.y * 32;
    int tx = threadIdx.x & 31, ty0 = threadIdx.x >> 5;
    #pragma unroll
    for (int i = 0; i < 4; i++)
        tile[ty0 + 8 * i][tx] = W[(size_t)(kb + ty0 + 8 * i) * Nd + nb + tx];
    __syncthreads();
    #pragma unroll
    for (int i = 0; i < 4; i++) {
        int r = ty0 + 8 * i;
        float v = tile[tx][r];
        __nv_bfloat16 h = __float2bfloat16_rn(v);
        __nv_bfloat16 l = __float2bfloat16_rn(v - __bfloat162float(h));
        size_t o = (size_t)(nb + r) * Kd + kb + tx;
        hi[o] = h;
        lo[o] = l;
    }
}

// ================= bf16-split HMMA GEMM (unchanged from R7) =================
#define SM_STRIDE 80
#define SM_SPLIT 10240
#define SM_BUF 40960
#define SMEMB 81920

template<int ACT>
__global__ __launch_bounds__(256, 1)
void gemm_mma(const __nv_bfloat16* __restrict__ Ahi, const __nv_bfloat16* __restrict__ Alo,
              const __nv_bfloat16* __restrict__ Bhi, const __nv_bfloat16* __restrict__ Blo,
              const float* __restrict__ bias, float* __restrict__ C,
              int M, int N, int K,
              const __nv_bfloat16* B2hi, const __nv_bfloat16* B2lo, float* C2) {
    extern __shared__ char smem[];
    if (blockIdx.z) { Bhi = B2hi; Blo = B2lo; C = C2; }
    const int tid = threadIdx.x, wid = tid >> 5, lane = tid & 31;
    const int m0 = blockIdx.y * 128, n0 = blockIdx.x * 128;
    const int wm = wid >> 2, wn = wid & 3;
    const uint32_t sb = smem_u32(smem);

    const int r0c = tid >> 2, c0c = (tid & 3);
    const int r1c = (tid + 256) >> 2, c1c = (tid & 3);

    auto fill = [&](int buf, int kc) {
        const int k0 = kc << 5;
        const uint32_t s0 = sb + buf * SM_BUF;
        uint32_t so0 = r0c * SM_STRIDE + c0c * 16;
        uint32_t so1 = r1c * SM_STRIDE + c1c * 16;
        const __nv_bfloat16* a0 = Ahi + (size_t)(m0 + r0c) * K + k0 + c0c * 8;
        const __nv_bfloat16* a1 = Ahi + (size_t)(m0 + r1c) * K + k0 + c1c * 8;
        const __nv_bfloat16* b0 = Bhi + (size_t)(n0 + r0c) * K + k0 + c0c * 8;
        const __nv_bfloat16* b1 = Bhi + (size_t)(n0 + r1c) * K + k0 + c1c * 8;
        size_t dAL = (size_t)(Alo - Ahi), dBL = (size_t)(Blo - Bhi);
        CP16(s0 + so0, a0); CP16(s0 + so1, a1);
        CP16(s0 + SM_SPLIT + so0, a0 + dAL); CP16(s0 + SM_SPLIT + so1, a1 + dAL);
        CP16(s0 + 2 * SM_SPLIT + so0, b0); CP16(s0 + 2 * SM_SPLIT + so1, b1);
        CP16(s0 + 3 * SM_SPLIT + so0, b0 + dBL); CP16(s0 + 3 * SM_SPLIT + so1, b1 + dBL);
        CP_COMMIT();
    };

    float acc[4][4][4] = {};
    const int KC = K >> 5;
    fill(0, 0);
    for (int kc = 0; kc < KC; kc++) {
        if (kc + 1 < KC) { fill((kc + 1) & 1, kc + 1); CP_WAIT(1); }
        else             { CP_WAIT(0); }
        __syncthreads();
        const uint32_t base = sb + (kc & 1) * SM_BUF;
        const uint32_t lrow = (lane & 15), lcol = (lane >> 4) * 16;
        #pragma unroll
        for (int kh = 0; kh < 2; kh++) {
            uint32_t ahi[4][4], alo[4][4], bhi[2][4], blo[2][4];
            #pragma unroll
            for (int mt = 0; mt < 4; mt++) {
                uint32_t ra = base + (wm * 64 + mt * 16 + lrow) * SM_STRIDE + kh * 32 + lcol;
                ldsm_x4(ahi[mt], ra);
                ldsm_x4(alo[mt], ra + SM_SPLIT);
            }
            #pragma unroll
            for (int nt = 0; nt < 2; nt++) {
                uint32_t rb = base + 2 * SM_SPLIT + (wn * 32 + nt * 16 + lrow) * SM_STRIDE + kh * 32 + lcol;
                ldsm_x4(bhi[nt], rb);
                ldsm_x4(blo[nt], rb + SM_SPLIT);
            }
            #pragma unroll
            for (int mt = 0; mt < 4; mt++)
                #pragma unroll
                for (int j = 0; j < 4; j++) {
                    uint32_t bh0 = bhi[j >> 1][j & 1], bh1 = bhi[j >> 1][2 + (j & 1)];
                    uint32_t bl0 = blo[j >> 1][j & 1], bl1 = blo[j >> 1][2 + (j & 1)];
                    mma16816(acc[mt][j], ahi[mt], bh0, bh1);
                    mma16816(acc[mt][j], ahi[mt], bl0, bl1);
                    mma16816(acc[mt][j], alo[mt], bh0, bh1);
                }
        }
        __syncthreads();
    }

    const int erow = m0 + wm * 64 + (lane >> 2);
    const int ecol = n0 + wn * 32 + (lane & 3) * 2;
    #pragma unroll
    for (int mt = 0; mt < 4; mt++)
        #pragma unroll
        for (int j = 0; j < 4; j++) {
            int r = erow + mt * 16, c = ecol + j * 8;
            float v0 = acc[mt][j][0], v1 = acc[mt][j][1];
            float v2 = acc[mt][j][2], v3 = acc[mt][j][3];
            if (ACT) {
                float b0 = bias[c], b1 = bias[c + 1];
                v0 += b0; v1 += b1; v2 += b0; v3 += b1;
                v0 = v0 / (1.f + expf(-v0)); v1 = v1 / (1.f + expf(-v1));
                v2 = v2 / (1.f + expf(-v2)); v3 = v3 / (1.f + expf(-v3));
            }
            *(float2*)(C + (size_t)r * N + c)       = make_float2(v0, v1);
            *(float2*)(C + (size_t)(r + 8) * N + c) = make_float2(v2, v3);
        }
}

// ================= chunked causal EMA =================
__global__ void ema1_kernel(const float* __restrict__ x, float* __restrict__ l2,
                            float* __restrict__ carry) {
    int c = blockIdx.x;
    int d = blockIdx.y * 256 + threadIdx.x;
    const float beta = 0.9f, om = 0.1f;
    float m = 0.f;
    int t0 = c * 128;
    for (int t = t0; t < t0 + 128; t++) {
        m = beta * m + om * x[(size_t)t * D + d];
        l2[(size_t)t * D + d] = m;
    }
    carry[c * D + d] = m;
}
__global__ void ema2_kernel(const float* __restrict__ carry, float* __restrict__ cpref) {
    int d = blockIdx.x * 256 + threadIdx.x;
    const float b128 = 1.3900845e-06f;  // 0.9^128
    float p = 0.f;
    #pragma unroll
    for (int c = 0; c < 16; c++) {
        cpref[c * D + d] = p;
        p = carry[c * D + d] + b128 * p;
    }
}

// ================= router =================
__global__ void router_kernel(const float* __restrict__ h, const float* __restrict__ Wr2,
                              const float* __restrict__ br2, float* __restrict__ lam) {
    int t = blockIdx.x * (blockDim.x >> 5) + (threadIdx.x >> 5);
    int lane = threadIdx.x & 31;
    if (t >= T) return;
    const float* hp = h + (size_t)t * DH;
    float z0 = 0.f, z1 = 0.f;
    for (int i = lane; i < DH; i += 32) {
        float hv = hp[i];
        z0 += hv * Wr2[i * 2 + 0];
        z1 += hv * Wr2[i * 2 + 1];
    }
    #pragma unroll
    for (int off = 16; off; off >>= 1) {
        z0 += __shfl_xor_sync(0xffffffffu, z0, off);
        z1 += __shfl_xor_sync(0xffffffffu, z1, off);
    }
    if (lane == 0) {
        z0 += br2[0]; z1 += br2[1];
        float mx = fmaxf(z0, z1);
        float e0 = expf(z0 - mx), e1 = expf(z1 - mx);
        float inv = 1.f / (e0 + e1);
        lam[t * 2 + 0] = e0 * inv;
        lam[t * 2 + 1] = e1 * inv;
    }
}

// ====== fuse (with EMA carry fixup) ======
__global__ void fuse_kernel(const float* __restrict__ x, const float* __restrict__ l2,
                            const float* __restrict__ cpref, const float* __restrict__ lam,
                            float* __restrict__ fused) {
    int idx = blockIdx.x * blockDim.x + threadIdx.x;
    if (idx >= T * D) return;
    int t = idx >> 11, d = idx & 2047;
    int c = t >> 7, tl = t & 127;
    const float LOGB = -0.10536051565f;  // ln(0.9)
    float l2v = l2[idx] + __expf((float)(tl + 1) * LOGB) * cpref[c * D + d];
    fused[idx] = lam[t * 2] * x[idx] + lam[t * 2 + 1] * l2v;
}

// ================= RoPE in place =================
__global__ void rope_kernel(float* __restrict__ x, int heads) {
    int idx = blockIdx.x * blockDim.x + threadIdx.x;
    int total = T * heads * 64;
    if (idx >= total) return;
    int j = idx & 63;
    int hh = (idx >> 6) % heads;
    int t = idx / (heads * 64);
    float* p = x + (size_t)t * heads * HD + hh * HD;
    float inv = expf(-9.210340371976184f * (2.f * j / 128.f));
    float ang = (float)t * inv;
    float cs = cosf(ang), sn = sinf(ang);
    float a = p[j], b = p[j + 64];
    p[j]      = a * cs - b * sn;
    p[j + 64] = b * cs + a * sn;
}

// ================= tensor-core flash attention =================
// CTA: 64 q-rows of one head, 4 warps (M16 each). KV tiles 64 rows, double-buffered.
// SMEM layout (bytes): Qhi 0, Qlo 17408, then 2 KV buffers of
//   [Khi 0, Klo 17408, Vhi 34816, Vlo 52224] at 34816 + buf*69632. Row stride 272.
#define FA_STR 272
#define FA_QSZ 17408
#define FA_KVB 69632
#define FA_SMEM 174080

__global__ __launch_bounds__(128, 1)
void fattn_kernel(const __nv_bfloat16* __restrict__ Qhi, const __nv_bfloat16* __restrict__ Qlo,
                  const __nv_bfloat16* __restrict__ Khi, const __nv_bfloat16* __restrict__ Klo,
                  const __nv_bfloat16* __restrict__ Vhi, const __nv_bfloat16* __restrict__ Vlo,
                  float* __restrict__ o) {
    extern __shared__ char smem[];
    const int tid = threadIdx.x, wid = tid >> 5, lane = tid & 31;
    const int qt = (int)(gridDim.x - 1 - blockIdx.x);   // long CTAs first
    const int head = blockIdx.y;
    const int kvh = head >> 2;
    const uint32_t sb = smem_u32(smem);
    const int g = lane >> 2, tq = lane & 3;
    const uint32_t lrow = lane & 15, lcol = (lane >> 4) * 16;

    // ---- Q tile fill (hi/lo) ----
    {
        const size_t qoff = (size_t)(qt * 64) * D + head * HD;
        const size_t dQ = (size_t)(Qlo - Qhi);
        #pragma unroll
        for (int i = 0; i < 8; i++) {
            int idx = tid + i * 128;
            int r = idx >> 4, c = idx & 15;
            const __nv_bfloat16* src = Qhi + qoff + (size_t)r * D + c * 8;
            uint32_t dst = sb + r * FA_STR + c * 16;
            CP16(dst, src);
            CP16(dst + FA_QSZ, src + dQ);
        }
        CP_COMMIT();
    }

    const int kts = qt + 1;
    const size_t dK = (size_t)(Klo - Khi), dV = (size_t)(Vlo - Vhi);
    auto loadKV = [&](int kt) {
        const size_t koff = (size_t)(kt * 64) * KVD + kvh * HD;
        const uint32_t kb = sb + 2 * FA_QSZ + (kt & 1) * FA_KVB;
        #pragma unroll
        for (int i = 0; i < 8; i++) {
            int idx = tid + i * 128;
            int r = idx >> 4, c = idx & 15;
            size_t so = koff + (size_t)r * KVD + c * 8;
            uint32_t dst = kb + r * FA_STR + c * 16;
            CP16(dst,                 Khi + so);
            CP16(dst + FA_QSZ,        Khi + so + dK);
            CP16(dst + 2 * FA_QSZ,    Vhi + so);
            CP16(dst + 3 * FA_QSZ,    Vhi + so + dV);
        }
        CP_COMMIT();
    };
    loadKV(0);

    float m0 = -1e30f, m1 = -1e30f, l0 = 0.f, l1 = 0.f;
    float oa[16][4] = {};
    const float SC2 = 0.08838834764831845f * 1.4426950408889634f;  // scale * log2(e)

    for (int kt = 0; kt < kts; kt++) {
        if (kt + 1 < kts) { loadKV(kt + 1); CP_WAIT(1); }
        else              { CP_WAIT(0); }
        __syncthreads();
        const uint32_t kb = sb + 2 * FA_QSZ + (kt & 1) * FA_KVB;

        // ---- S = Q @ K^T (hi/lo: 3 MMAs) ----
        float s[8][4];
        #pragma unroll
        for (int nf = 0; nf < 8; nf++)
            s[nf][0] = s[nf][1] = s[nf][2] = s[nf][3] = 0.f;
        #pragma unroll
        for (int ks = 0; ks < 8; ks++) {
            uint32_t ahi[4], alo[4], bhi[4][4], blo[4][4];
            uint32_t ra = sb + (wid * 16 + lrow) * FA_STR + lcol + ks * 32;
            ldsm_x4(ahi, ra);
            ldsm_x4(alo, ra + FA_QSZ);
            #pragma unroll
            for (int bt = 0; bt < 4; bt++) {
                uint32_t rb = kb + (bt * 16 + lrow) * FA_STR + lcol + ks * 32;
                ldsm_x4(bhi[bt], rb);
                ldsm_x4(blo[bt], rb + FA_QSZ);
            }
            #pragma unroll
            for (int nf = 0; nf < 8; nf++) {
                uint32_t bh0 = bhi[nf >> 1][nf & 1], bh1 = bhi[nf >> 1][2 + (nf & 1)];
                uint32_t bl0 = blo[nf >> 1][nf & 1], bl1 = blo[nf >> 1][2 + (nf & 1)];
                mma16816(s[nf], ahi, bh0, bh1);
                mma16816(s[nf], ahi, bl0, bl1);
                mma16816(s[nf], alo, bh0, bh1);
            }
        }

        // ---- causal mask on diagonal tile ----
        if (kt == qt) {
            int r0 = wid * 16 + g;
            #pragma unroll
            for (int nf = 0; nf < 8; nf++) {
                int c0 = nf * 8 + tq * 2;
                if (c0 > r0)         s[nf][0] = -1e30f;
                if (c0 + 1 > r0)     s[nf][1] = -1e30f;
                if (c0 > r0 + 8)     s[nf][2] = -1e30f;
                if (c0 + 1 > r0 + 8) s[nf][3] = -1e30f;
            }
        }

        // ---- online softmax (raw scores; scale folded into ex2) ----
        float mx0 = -1e30f, mx1 = -1e30f;
        #pragma unroll
        for (int nf = 0; nf < 8; nf++) {
            mx0 = fmaxf(mx0, fmaxf(s[nf][0], s[nf][1]));
            mx1 = fmaxf(mx1, fmaxf(s[nf][2], s[nf][3]));
        }
        mx0 = fmaxf(mx0, __shfl_xor_sync(0xffffffffu, mx0, 1));
        mx0 = fmaxf(mx0, __shfl_xor_sync(0xffffffffu, mx0, 2));
        mx1 = fmaxf(mx1, __shfl_xor_sync(0xffffffffu, mx1, 1));
        mx1 = fmaxf(mx1, __shfl_xor_sync(0xffffffffu, mx1, 2));
        float mn0 = fmaxf(m0, mx0), mn1 = fmaxf(m1, mx1);
        float corr0 = ex2((m0 - mn0) * SC2);
        float corr1 = ex2((m1 - mn1) * SC2);
        m0 = mn0; m1 = mn1;
        l0 *= corr0; l1 *= corr1;
        #pragma unroll
        for (int nf = 0; nf < 8; nf++) {
            s[nf][0] = ex2((s[nf][0] - m0) * SC2);
            s[nf][1] = ex2((s[nf][1] - m0) * SC2);
            s[nf][2] = ex2((s[nf][2] - m1) * SC2);
            s[nf][3] = ex2((s[nf][3] - m1) * SC2);
            l0 += s[nf][0] + s[nf][1];
            l1 += s[nf][2] + s[nf][3];
        }
        #pragma unroll
        for (int nf = 0; nf < 16; nf++) {
            oa[nf][0] *= corr0; oa[nf][1] *= corr0;
            oa[nf][2] *= corr1; oa[nf][3] *= corr1;
        }

        // ---- O += P @ V (P hi/lo in regs, V hi/lo via ldmatrix.trans) ----
        #pragma unroll
        for (int pk = 0; pk < 4; pk++) {
            uint32_t pahi[4], palo[4];
            hilo2(s[2 * pk][0],     s[2 * pk][1],     pahi[0], palo[0]);
            hilo2(s[2 * pk][2],     s[2 * pk][3],     pahi[1], palo[1]);
            hilo2(s[2 * pk + 1][0], s[2 * pk + 1][1], pahi[2], palo[2]);
            hilo2(s[2 * pk + 1][2], s[2 * pk + 1][3], pahi[3], palo[3]);
            #pragma unroll
            for (int nb = 0; nb < 8; nb++) {
                uint32_t vh[4], vl[4];
                uint32_t va = kb + 2 * FA_QSZ + (pk * 16 + lrow) * FA_STR + nb * 32 + lcol;
                ldsm_x4_t(vh, va);
                ldsm_x4_t(vl, va + FA_QSZ);
                mma16816(oa[2 * nb],     pahi, vh[0], vh[1]);
                mma16816(oa[2 * nb],     pahi, vl[0], vl[1]);
                mma16816(oa[2 * nb],     palo, vh[0], vh[1]);
                mma16816(oa[2 * nb + 1], pahi, vh[2], vh[3]);
                mma16816(oa[2 * nb + 1], pahi, vl[2], vl[3]);
                mma16816(oa[2 * nb + 1], palo, vh[2], vh[3]);
            }
        }
        __syncthreads();
    }

    // ---- epilogue ----
    l0 += __shfl_xor_sync(0xffffffffu, l0, 1);
    l0 += __shfl_xor_sync(0xffffffffu, l0, 2);
    l1 += __shfl_xor_sync(0xffffffffu, l1, 1);
    l1 += __shfl_xor_sync(0xffffffffu, l1, 2);
    float inv0 = 1.f / l0, inv1 = 1.f / l1;
    int row0 = qt * 64 + wid * 16 + g;
    float* b0 = o + (size_t)row0 * D + head * HD + tq * 2;
    float* b1 = b0 + 8 * D;
    #pragma unroll
    for (int nf = 0; nf < 16; nf++) {
        *(float2*)(b0 + nf * 8) = make_float2(oa[nf][0] * inv0, oa[nf][1] * inv0);
        *(float2*)(b1 + nf * 8) = make_float2(oa[nf][2] * inv1, oa[nf][3] * inv1);
    }
}

// ================= launcher =================
extern "C" void kernel_launch(void* const* d_in, const int* in_sizes, int n_in,
                              void* d_out, int out_size) {
    const float* hs  = (const float*)d_in[0];
    const float* Wq  = (const float*)d_in[1];
    const float* Wk  = (const float*)d_in[2];
    const float* Wv  = (const float*)d_in[3];
    const float* Wo  = (const float*)d_in[4];
    const float* Wr1 = (const float*)d_in[5];
    const float* br1 = (const float*)d_in[6];
    const float* Wr2 = (const float*)d_in[7];
    const float* br2 = (const float*)d_in[8];
    float* out = (float*)d_out;

    float* S;
    cudaGetSymbolAddress((void**)&S, g_scratch);
    float* q     = S;
    float* l2    = S + 4 * MEG;
    float* h     = S + 8 * MEG;
    float* fused = S + 10 * MEG;
    float* kbuf  = S + 14 * MEG;
    float* vbuf  = S + 15 * MEG;
    float* ao    = S + 16 * MEG;
    float* lam   = S + 20 * MEG;
    float* carry = lam + 4096;
    float* cpref = carry + 32768;
    __nv_bfloat16* Ahi = (__nv_bfloat16*)(S + 20 * MEG + 131072);
    __nv_bfloat16* Alo = (__nv_bfloat16*)(S + 22 * MEG + 131072);
    __nv_bfloat16* Whi = (__nv_bfloat16*)(S + 24 * MEG + 131072);
    __nv_bfloat16* Wlo = (__nv_bfloat16*)(S + 26 * MEG + 131072);
    __nv_bfloat16* QhiB = (__nv_bfloat16*)(S + 29 * MEG);
    __nv_bfloat16* QloB = (__nv_bfloat16*)(S + 31 * MEG);
    __nv_bfloat16* KhiB = (__nv_bfloat16*)(S + 33 * MEG);
    __nv_bfloat16* KloB = (__nv_bfloat16*)(S + 33 * MEG + 512 * 1024);
    __nv_bfloat16* VhiB = (__nv_bfloat16*)(S + 34 * MEG);
    __nv_bfloat16* VloB = (__nv_bfloat16*)(S + 34 * MEG + 512 * 1024);

    cudaFuncSetAttribute(gemm_mma<0>, cudaFuncAttributeMaxDynamicSharedMemorySize, SMEMB);
    cudaFuncSetAttribute(gemm_mma<1>, cudaFuncAttributeMaxDynamicSharedMemorySize, SMEMB);
    cudaFuncSetAttribute(fattn_kernel, cudaFuncAttributeMaxDynamicSharedMemorySize, FA_SMEM);

    // ---- q = hs @ Wq ----
    conv_a<<<(T * D / 4 + 255) / 256, 256>>>(hs, Ahi, Alo, T * D / 4);
    conv_wt<<<dim3(D / 32, D / 32), 256>>>(Wq, Whi, Wlo, D, D);
    gemm_mma<0><<<dim3(D / 128, T / 128, 1), 256, SMEMB>>>(
        Ahi, Alo, Whi, Wlo, nullptr, q, T, D, D, nullptr, nullptr, nullptr);

    // ---- EMA ----
    ema1_kernel<<<dim3(16, 8), 256>>>(hs, l2, carry);
    ema2_kernel<<<8, 256>>>(carry, cpref);

    // ---- h = silu(q @ Wr1 + br1) ----
    conv_a<<<(T * D / 4 + 255) / 256, 256>>>(q, Ahi, Alo, T * D / 4);
    conv_wt<<<dim3(DH / 32, D / 32), 256>>>(Wr1, Whi, Wlo, D, DH);
    gemm_mma<1><<<dim3(DH / 128, T / 128, 1), 256, SMEMB>>>(
        Ahi, Alo, Whi, Wlo, br1, h, T, DH, D, nullptr, nullptr, nullptr);

    // ---- lam, fused ----
    router_kernel<<<T / 8, 256>>>(h, Wr2, br2, lam);
    fuse_kernel<<<(T * D + 255) / 256, 256>>>(hs, l2, cpref, lam, fused);

    // ---- k = fused @ Wk, v = fused @ Wv ----
    conv_a<<<(T * D / 4 + 255) / 256, 256>>>(fused, Ahi, Alo, T * D / 4);
    __nv_bfloat16* WkHi = Whi;
    __nv_bfloat16* WkLo = Whi + KVD * D;
    __nv_bfloat16* WvHi = Wlo;
    __nv_bfloat16* WvLo = Wlo + KVD * D;
    conv_wt<<<dim3(KVD / 32, D / 32), 256>>>(Wk, WkHi, WkLo, D, KVD);
    conv_wt<<<dim3(KVD / 32, D / 32), 256>>>(Wv, WvHi, WvLo, D, KVD);
    gemm_mma<0><<<dim3(KVD / 128, T / 128, 2), 256, SMEMB>>>(
        Ahi, Alo, WkHi, WkLo, nullptr, kbuf, T, KVD, D, WvHi, WvLo, vbuf);

    // ---- RoPE ----
    rope_kernel<<<(T * NH * 64 + 255) / 256, 256>>>(q, NH);
    rope_kernel<<<(T * NKVH * 64 + 255) / 256, 256>>>(kbuf, NKVH);

    // ---- convert q/k/v to bf16 hi/lo for flash attention ----
    conv_a<<<(T * D / 4 + 255) / 256, 256>>>(q, QhiB, QloB, T * D / 4);
    conv_a<<<(T * KVD / 4 + 255) / 256, 256>>>(kbuf, KhiB, KloB, T * KVD / 4);
    conv_a<<<(T * KVD / 4 + 255) / 256, 256>>>(vbuf, VhiB, VloB, T * KVD / 4);

    // ---- flash attention ----
    fattn_kernel<<<dim3(T / 64, NH), 128, FA_SMEM>>>(QhiB, QloB, KhiB, KloB, VhiB, VloB, ao);

    // ---- out = ao @ Wo ----
    conv_a<<<(T * D / 4 + 255) / 256, 256>>>(ao, Ahi, Alo, T * D / 4);
    conv_wt<<<dim3(D / 32, D / 32), 256>>>(Wo, Whi, Wlo, D, D);
    gemm_mma<0><<<dim3(D / 128, T / 128, 1), 256, SMEMB>>>(
        Ahi, Alo, Whi, Wlo, nullptr, out, T, D, D, nullptr, nullptr, nullptr);
}